// round 10
// baseline (speedup 1.0000x reference)
#include <cuda_runtime.h>
#include <math.h>
#include <cstdint>

#define D_DIM 1536
#define M_TOT 4096
#define NCH   12            // 1536 / 128 int8 per chunk
#define TM 128
#define TN 64
#define NTILES ((M_TOT / TM) * (D_DIM / TN))   // 768
#define NGEO 9

__device__ int8_t g_Ah[(size_t)M_TOT * D_DIM];
__device__ int8_t g_Al[(size_t)M_TOT * D_DIM];
__device__ int8_t g_Bh[(size_t)D_DIM * D_DIM];
__device__ int8_t g_Bl[(size_t)D_DIM * D_DIM];
__device__ float  g_sA[M_TOT];
__device__ float  g_sB[D_DIM];
__device__ float  g_h[(size_t)M_TOT * D_DIM];

// ---------------------------------------------------------------------------
// per-row 15-bit quantization: q = round(v*16256/rowmax), q = 128*hi + lo
// ---------------------------------------------------------------------------
template<bool ISW>
__global__ void quant_kernel(const float* __restrict__ src)
{
    const int row  = blockIdx.x * 8 + (threadIdx.x >> 5);
    const int lane = threadIdx.x & 31;
    const float4* xr = (const float4*)(src + (size_t)row * D_DIM);

    float4 v[12];
    float mx = 0.f;
    #pragma unroll
    for (int i = 0; i < 12; i++) {
        v[i] = xr[lane + 32 * i];
        mx = fmaxf(mx, fmaxf(fmaxf(fabsf(v[i].x), fabsf(v[i].y)),
                             fmaxf(fabsf(v[i].z), fabsf(v[i].w))));
    }
    #pragma unroll
    for (int o = 16; o; o >>= 1) mx = fmaxf(mx, __shfl_xor_sync(0xFFFFFFFFu, mx, o));
    mx = fmaxf(mx, 1e-30f);
    const float s   = mx * (1.0f / 16256.0f);
    const float inv = 16256.0f / mx;
    if (lane == 0) { if (ISW) g_sB[row] = s; else g_sA[row] = s; }

    char4* hp = (char4*)((ISW ? g_Bh : g_Ah) + (size_t)row * D_DIM);
    char4* lp = (char4*)((ISW ? g_Bl : g_Al) + (size_t)row * D_DIM);
    #pragma unroll
    for (int i = 0; i < 12; i++) {
        int q0 = __float2int_rn(v[i].x * inv);
        int q1 = __float2int_rn(v[i].y * inv);
        int q2 = __float2int_rn(v[i].z * inv);
        int q3 = __float2int_rn(v[i].w * inv);
        int h0 = (q0 + 64) >> 7, l0 = q0 - (h0 << 7);
        int h1 = (q1 + 64) >> 7, l1 = q1 - (h1 << 7);
        int h2 = (q2 + 64) >> 7, l2 = q2 - (h2 << 7);
        int h3 = (q3 + 64) >> 7, l3 = q3 - (h3 << 7);
        hp[lane + 32 * i] = make_char4((char)h0, (char)h1, (char)h2, (char)h3);
        lp[lane + 32 * i] = make_char4((char)l0, (char)l1, (char)l2, (char)l3);
    }
}

// ---------------------------------------------------------------------------
// Persistent IMMA GEMM:  C = sA·sB·(16384·HH + 128·(HL + LH)),  GELU fused
// ---------------------------------------------------------------------------
#define SWZ(o) ((o) ^ (((o) >> 3) & 0x70))

__device__ __forceinline__ uint32_t s2u(const void* p) {
    uint32_t a;
    asm("{ .reg .u64 t; cvta.to.shared.u64 t, %1; cvt.u32.u64 %0, t; }"
        : "=r"(a) : "l"(p));
    return a;
}
__device__ __forceinline__ void cp16(uint32_t dst, const void* src) {
    asm volatile("cp.async.cg.shared.global [%0], [%1], 16;\n"
                 :: "r"(dst), "l"(src));
}
__device__ __forceinline__ void ldm4(uint32_t* r, uint32_t addr) {
    asm volatile("ldmatrix.sync.aligned.m8n8.x4.shared.b16 {%0,%1,%2,%3}, [%4];"
                 : "=r"(r[0]), "=r"(r[1]), "=r"(r[2]), "=r"(r[3]) : "r"(addr));
}
__device__ __forceinline__ void imma16832(int* c, const uint32_t* a, const uint32_t* b) {
    asm volatile("mma.sync.aligned.m16n8k32.row.col.s32.s8.s8.s32 "
                 "{%0,%1,%2,%3}, {%4,%5,%6,%7}, {%8,%9}, {%0,%1,%2,%3};"
                 : "+r"(c[0]), "+r"(c[1]), "+r"(c[2]), "+r"(c[3])
                 : "r"(a[0]), "r"(a[1]), "r"(a[2]), "r"(a[3]),
                   "r"(b[0]), "r"(b[1]));
}

static constexpr int A_T  = TM * 128;          // 16 KB (128 rows x 128 int8)
static constexpr int B_T  = TN * 128;          // 8 KB
static constexpr int STAGE_B = 2 * A_T + 2 * B_T;   // 48 KB: AH AL BH BL
static constexpr int SMEM_BYTES = 2 * STAGE_B + 1024;

__global__ __launch_bounds__(256, 2)
void gemm_mma_kernel(const float* __restrict__ b1)
{
    extern __shared__ char smem[];
    const uint32_t sb = (s2u(smem) + 1023) & ~1023u;

    const int tid  = threadIdx.x;
    const int wid  = tid >> 5, lane = tid & 31;
    const int wm   = wid & 3;          // 4 warps in M (32 rows)
    const int wn   = wid >> 2;         // 2 warps in N (32 cols)

    const uint32_t STG[2] = { sb, sb + STAGE_B };

    uint32_t a_off[2], a_xr[2];
    #pragma unroll
    for (int i = 0; i < 2; i++) {
        int row = wm * 32 + i * 16 + (lane & 15);
        a_off[i] = row * 128;
        a_xr[i]  = (row & 7) << 4;
    }
    const uint32_t a_kh = (lane >> 4) * 16;

    uint32_t b_off[2], b_xr[2];
    #pragma unroll
    for (int j2 = 0; j2 < 2; j2++) {
        int row = wn * 32 + j2 * 16 + (lane & 7) + ((lane >> 4) & 1) * 8;
        b_off[j2] = row * 128;
        b_xr[j2]  = (row & 7) << 4;
    }
    const uint32_t b_kh = ((lane >> 3) & 1) * 16;

    const int l_r  = tid >> 3;      // 0..31
    const int l_c8 = tid & 7;

    for (int t = blockIdx.x; t < NTILES; t += gridDim.x) {
        const int bm = (t / (D_DIM / TN)) * TM;
        const int bn = (t % (D_DIM / TN)) * TN;

        auto load_stage = [&](int s, int k0) {
            const uint32_t st = STG[s];
            #pragma unroll
            for (int i = 0; i < 4; i++) {
                const int r = l_r + i * 32;
                uint32_t dsw = SWZ(r * 128 + l_c8 * 16);
                const int8_t* arow = g_Ah + (size_t)(bm + r) * D_DIM + k0 + l_c8 * 16;
                const int8_t* lrow = g_Al + (size_t)(bm + r) * D_DIM + k0 + l_c8 * 16;
                cp16(st       + dsw, arow);
                cp16(st + A_T + dsw, lrow);
            }
            #pragma unroll
            for (int i = 0; i < 2; i++) {
                const int r = l_r + i * 32;
                uint32_t dsw = SWZ(r * 128 + l_c8 * 16);
                const int8_t* brow = g_Bh + (size_t)(bn + r) * D_DIM + k0 + l_c8 * 16;
                const int8_t* mrow = g_Bl + (size_t)(bn + r) * D_DIM + k0 + l_c8 * 16;
                cp16(st + 2 * A_T       + dsw, brow);
                cp16(st + 2 * A_T + B_T + dsw, mrow);
            }
        };

        int accH[2][4][4] = {};
        int accX[2][4][4] = {};

        load_stage(0, 0);
        asm volatile("cp.async.commit_group;" ::: "memory");

        for (int ch = 0; ch < NCH; ch++) {
            const int cur = ch & 1;
            asm volatile("cp.async.wait_group 0;" ::: "memory");
            __syncthreads();

            if (ch + 1 < NCH) {
                load_stage(cur ^ 1, (ch + 1) * 128);
                asm volatile("cp.async.commit_group;" ::: "memory");
            }

            const uint32_t AH = STG[cur];
            const uint32_t AL = AH + A_T;
            const uint32_t BH = AH + 2 * A_T;
            const uint32_t BL = BH + B_T;

            #pragma unroll
            for (int ks = 0; ks < 4; ks++) {
                const uint32_t kb = ks * 32;           // 32 bytes = k32 step
                uint32_t ah[2][4], al[2][4], bh[2][4], bl[2][4];
                #pragma unroll
                for (int i = 0; i < 2; i++) {
                    uint32_t off = a_off[i] + ((kb + a_kh) ^ a_xr[i]);
                    ldm4(ah[i], AH + off);
                    ldm4(al[i], AL + off);
                }
                #pragma unroll
                for (int j2 = 0; j2 < 2; j2++) {
                    uint32_t off = b_off[j2] + ((kb + b_kh) ^ b_xr[j2]);
                    ldm4(bh[j2], BH + off);
                    ldm4(bl[j2], BL + off);
                }
                #pragma unroll
                for (int i = 0; i < 2; i++)
                    #pragma unroll
                    for (int j = 0; j < 4; j++)
                        imma16832(accH[i][j], ah[i], bh[j >> 1] + (j & 1) * 2);
                #pragma unroll
                for (int i = 0; i < 2; i++)
                    #pragma unroll
                    for (int j = 0; j < 4; j++)
                        imma16832(accX[i][j], ah[i], bl[j >> 1] + (j & 1) * 2);
                #pragma unroll
                for (int i = 0; i < 2; i++)
                    #pragma unroll
                    for (int j = 0; j < 4; j++)
                        imma16832(accX[i][j], al[i], bh[j >> 1] + (j & 1) * 2);
            }
        }

        // epilogue: dequant + bias + exact GELU
        const int r0 = lane >> 2;
        const int c0 = (lane & 3) * 2;
        #pragma unroll
        for (int i = 0; i < 2; i++) {
            const int m0 = bm + wm * 32 + i * 16 + r0;
            #pragma unroll
            for (int j = 0; j < 4; j++) {
                const int col = bn + wn * 32 + j * 8 + c0;
                const float bb0 = __ldg(&b1[col]);
                const float bb1 = __ldg(&b1[col + 1]);
                const float sb0 = __ldg(&g_sB[col]);
                const float sb1 = __ldg(&g_sB[col + 1]);
                #pragma unroll
                for (int half = 0; half < 2; half++) {
                    const int m = m0 + half * 8;
                    const float sa = __ldg(&g_sA[m]);
                    float v0 = sa * sb0 * (16384.0f * (float)accH[i][j][half * 2 + 0]
                                         + 128.0f  * (float)accX[i][j][half * 2 + 0]) + bb0;
                    float v1 = sa * sb1 * (16384.0f * (float)accH[i][j][half * 2 + 1]
                                         + 128.0f  * (float)accX[i][j][half * 2 + 1]) + bb1;
                    float g0 = 0.5f * v0 * (1.0f + erff(v0 * 0.70710678118654752440f));
                    float g1 = 0.5f * v1 * (1.0f + erff(v1 * 0.70710678118654752440f));
                    *(float2*)(g_h + (size_t)m * D_DIM + col) = make_float2(g0, g1);
                }
            }
        }
    }
}

// ---------------------------------------------------------------------------
// Kernel B: 4 tokens per block — LN -> p[0:9] -> geometry (R8 version)
// ---------------------------------------------------------------------------
__constant__ float c_bb[3][3] = {
    {-0.525f, 1.363f, 0.0f},
    { 0.0f,   0.0f,   0.0f},
    { 1.526f, 0.0f,   0.0f}
};

__global__ __launch_bounds__(256)
void ln_head_kernel(const float* __restrict__ ln_g,
                    const float* __restrict__ ln_b,
                    const float* __restrict__ w2,
                    const float* __restrict__ b2,
                    const float* __restrict__ affine,
                    const int*   __restrict__ mask,
                    float* __restrict__ out)
{
    const int tid  = threadIdx.x;
    const int wid  = tid >> 5, lane = tid & 31;
    const int sub  = tid >> 6;
    const int st   = tid & 63;
    const int row0 = blockIdx.x * 4;
    const int row  = row0 + sub;

    __shared__ float sh[4][D_DIM];
    __shared__ float red[16];
    __shared__ float pbuf[4][12];

    const float4* h4 = (const float4*)(g_h + (size_t)row * D_DIM);
    float4 l[6];
    float s = 0.0f;
    #pragma unroll
    for (int j = 0; j < 6; j++) {
        l[j] = h4[st + j * 64];
        s += (l[j].x + l[j].y) + (l[j].z + l[j].w);
    }
    #pragma unroll
    for (int o = 16; o; o >>= 1) s += __shfl_xor_sync(0xFFFFFFFFu, s, o);
    if (lane == 0) red[wid] = s;
    __syncthreads();
    const float mu = (red[sub * 2] + red[sub * 2 + 1]) * (1.0f / D_DIM);

    float s2 = 0.0f;
    #pragma unroll
    for (int j = 0; j < 6; j++) {
        float dx = l[j].x - mu, dy = l[j].y - mu, dz = l[j].z - mu, dw = l[j].w - mu;
        s2 += dx * dx + dy * dy + dz * dz + dw * dw;
    }
    #pragma unroll
    for (int o = 16; o; o >>= 1) s2 += __shfl_xor_sync(0xFFFFFFFFu, s2, o);
    __syncthreads();
    if (lane == 0) red[wid] = s2;
    __syncthreads();
    const float var = (red[sub * 2] + red[sub * 2 + 1]) * (1.0f / D_DIM);
    const float inv = rsqrtf(var + 1e-5f);

    const float4* g4 = (const float4*)ln_g;
    const float4* b4 = (const float4*)ln_b;
    #pragma unroll
    for (int j = 0; j < 6; j++) {
        const int idx = st + j * 64;
        float4 g = g4[idx], b = b4[idx];
        float4 r;
        r.x = (l[j].x - mu) * inv * g.x + b.x;
        r.y = (l[j].y - mu) * inv * g.y + b.y;
        r.z = (l[j].z - mu) * inv * g.z + b.z;
        r.w = (l[j].w - mu) * inv * g.w + b.w;
        ((float4*)sh[sub])[idx] = r;
    }
    __syncthreads();

    for (int o = wid; o < NGEO; o += 8) {
        const float4* w4 = (const float4*)(w2 + (size_t)o * D_DIM);
        float a0 = 0.f, a1 = 0.f, a2 = 0.f, a3 = 0.f;
        #pragma unroll 4
        for (int d4 = lane; d4 < D_DIM / 4; d4 += 32) {
            float4 w = w4[d4];
            float4 h0 = ((const float4*)sh[0])[d4];
            float4 h1 = ((const float4*)sh[1])[d4];
            float4 h2 = ((const float4*)sh[2])[d4];
            float4 h3 = ((const float4*)sh[3])[d4];
            a0 = fmaf(w.x, h0.x, fmaf(w.y, h0.y, fmaf(w.z, h0.z, fmaf(w.w, h0.w, a0))));
            a1 = fmaf(w.x, h1.x, fmaf(w.y, h1.y, fmaf(w.z, h1.z, fmaf(w.w, h1.w, a1))));
            a2 = fmaf(w.x, h2.x, fmaf(w.y, h2.y, fmaf(w.z, h2.z, fmaf(w.w, h2.w, a2))));
            a3 = fmaf(w.x, h3.x, fmaf(w.y, h3.y, fmaf(w.z, h3.z, fmaf(w.w, h3.w, a3))));
        }
        #pragma unroll
        for (int off = 16; off; off >>= 1) {
            a0 += __shfl_xor_sync(0xFFFFFFFFu, a0, off);
            a1 += __shfl_xor_sync(0xFFFFFFFFu, a1, off);
            a2 += __shfl_xor_sync(0xFFFFFFFFu, a2, off);
            a3 += __shfl_xor_sync(0xFFFFFFFFu, a3, off);
        }
        if (lane == 0) {
            const float bb = b2[o];
            pbuf[0][o] = a0 + bb;
            pbuf[1][o] = a1 + bb;
            pbuf[2][o] = a2 + bb;
            pbuf[3][o] = a3 + bb;
        }
    }
    __syncthreads();

    if (tid < 4) {
        const int r = row0 + tid;
        const float* p = pbuf[tid];
        float trans[3], xv[3], yv[3];
        #pragma unroll
        for (int i = 0; i < 3; i++) {
            trans[i] = p[i] * 10.0f;
            xv[i]    = p[3 + i];
            yv[i]    = p[6 + i];
        }
        float xn = sqrtf(xv[0]*xv[0] + xv[1]*xv[1] + xv[2]*xv[2]) + 1e-5f;
        float yn = sqrtf(yv[0]*yv[0] + yv[1]*yv[1] + yv[2]*yv[2]) + 1e-5f;
        #pragma unroll
        for (int i = 0; i < 3; i++) { xv[i] /= xn; yv[i] /= yn; }

        float ax[3] = { -xv[0], -xv[1], -xv[2] };
        float n0 = rsqrtf(ax[0]*ax[0] + ax[1]*ax[1] + ax[2]*ax[2] + 1e-12f);
        float e0[3] = { ax[0]*n0, ax[1]*n0, ax[2]*n0 };
        float c = e0[0]*yv[0] + e0[1]*yv[1] + e0[2]*yv[2];
        float e1[3] = { yv[0] - e0[0]*c, yv[1] - e0[1]*c, yv[2] - e0[2]*c };
        float n1 = rsqrtf(e1[0]*e1[0] + e1[1]*e1[1] + e1[2]*e1[2] + 1e-12f);
        e1[0] *= n1; e1[1] *= n1; e1[2] *= n1;
        float e2[3] = { e0[1]*e1[2] - e0[2]*e1[1],
                        e0[2]*e1[0] - e0[0]*e1[2],
                        e0[0]*e1[1] - e0[1]*e1[0] };

        float Ru[3][3] = {
            { e0[0], e1[0], e2[0] },
            { e0[1], e1[1], e2[1] },
            { e0[2], e1[2], e2[2] }
        };
        float tu[3] = { trans[0], trans[1], trans[2] };

        if (mask[r] == 0) {
            #pragma unroll
            for (int i = 0; i < 3; i++) {
                #pragma unroll
                for (int j = 0; j < 3; j++) Ru[i][j] = (i == j) ? 1.0f : 0.0f;
                tu[i] = 0.0f;
            }
        }

        const float* af = affine + (size_t)r * 12;
        float R0[3][3], t0[3];
        #pragma unroll
        for (int i = 0; i < 3; i++) {
            #pragma unroll
            for (int j = 0; j < 3; j++) R0[i][j] = af[i * 3 + j];
            t0[i] = af[9 + i];
        }

        float R[3][3], tt[3];
        #pragma unroll
        for (int i = 0; i < 3; i++) {
            #pragma unroll
            for (int j = 0; j < 3; j++) {
                float a = 0.0f;
                #pragma unroll
                for (int k = 0; k < 3; k++) a = fmaf(R0[i][k], Ru[k][j], a);
                R[i][j] = a;
            }
            float ta = t0[i];
            #pragma unroll
            for (int j = 0; j < 3; j++) ta = fmaf(R0[i][j], tu[j], ta);
            tt[i] = ta;
        }

        float* ao = out + (size_t)r * 12;
        #pragma unroll
        for (int i = 0; i < 3; i++)
            #pragma unroll
            for (int j = 0; j < 3; j++) ao[i * 3 + j] = R[i][j];
        #pragma unroll
        for (int i = 0; i < 3; i++) ao[9 + i] = tt[i];

        float* po = out + (size_t)M_TOT * 12 + (size_t)r * 9;
        #pragma unroll
        for (int a = 0; a < 3; a++) {
            #pragma unroll
            for (int i = 0; i < 3; i++) {
                float v = tt[i];
                #pragma unroll
                for (int j = 0; j < 3; j++) v = fmaf(R[i][j], c_bb[a][j], v);
                po[a * 3 + i] = v;
            }
        }
    }
}

// ---------------------------------------------------------------------------
extern "C" void kernel_launch(void* const* d_in, const int* in_sizes, int n_in,
                              void* d_out, int out_size)
{
    const float* x      = (const float*)d_in[0];
    const float* affine = (const float*)d_in[1];
    const int*   amask  = (const int*)  d_in[2];
    const float* w1     = (const float*)d_in[3];
    const float* b1     = (const float*)d_in[4];
    const float* ln_g   = (const float*)d_in[5];
    const float* ln_b   = (const float*)d_in[6];
    const float* w2     = (const float*)d_in[7];
    const float* b2     = (const float*)d_in[8];
    float* out = (float*)d_out;

    cudaFuncSetAttribute(gemm_mma_kernel,
                         cudaFuncAttributeMaxDynamicSharedMemorySize, SMEM_BYTES);

    int sms = 148;
    cudaDeviceGetAttribute(&sms, cudaDevAttrMultiProcessorCount, 0);

    quant_kernel<false><<<M_TOT / 8, 256>>>(x);
    quant_kernel<true><<<D_DIM / 8, 256>>>(w1);

    gemm_mma_kernel<<<sms * 2, 256, SMEM_BYTES>>>(b1);

    ln_head_kernel<<<M_TOT / 4, 256>>>(ln_g, ln_b, w2, b2, affine, amask, out);
}

// round 11
// speedup vs baseline: 2.5890x; 2.5890x over previous
#include <cuda_runtime.h>
#include <cuda_bf16.h>
#include <math.h>
#include <cstdint>

#define D_DIM 1536
#define M_TOT 4096
#define K2    3072          // [hi | lo]
#define NCH   24            // 1536 / 64
#define TM 128
#define TN 64
#define NTILES ((M_TOT / TM) * (D_DIM / TN))   // 768
#define NGEO 9

__device__ __nv_bfloat16 g_A[(size_t)M_TOT * K2];
__device__ __nv_bfloat16 g_B[(size_t)D_DIM * K2];
__device__ float         g_h[(size_t)M_TOT * D_DIM];

// ---------------------------------------------------------------------------
// merged split-to-bf16 conversion kernel (x then w1 by flat float4 index)
// ---------------------------------------------------------------------------
__device__ __forceinline__ uint2 split_hi(float4 v) {
    __nv_bfloat162 h01 = __nv_bfloat162(__float2bfloat16(v.x), __float2bfloat16(v.y));
    __nv_bfloat162 h23 = __nv_bfloat162(__float2bfloat16(v.z), __float2bfloat16(v.w));
    uint2 r; r.x = *(uint32_t*)&h01; r.y = *(uint32_t*)&h23; return r;
}
__device__ __forceinline__ uint2 split_lo(float4 v) {
    float lx = v.x - __bfloat162float(__float2bfloat16(v.x));
    float ly = v.y - __bfloat162float(__float2bfloat16(v.y));
    float lz = v.z - __bfloat162float(__float2bfloat16(v.z));
    float lw = v.w - __bfloat162float(__float2bfloat16(v.w));
    __nv_bfloat162 l01 = __nv_bfloat162(__float2bfloat16(lx), __float2bfloat16(ly));
    __nv_bfloat162 l23 = __nv_bfloat162(__float2bfloat16(lz), __float2bfloat16(lw));
    uint2 r; r.x = *(uint32_t*)&l01; r.y = *(uint32_t*)&l23; return r;
}

#define XCNT (M_TOT * D_DIM / 4)
#define WCNT (D_DIM * D_DIM / 4)

__global__ void conv_all_kernel(const float* __restrict__ x,
                                const float* __restrict__ w1)
{
    const int i = blockIdx.x * blockDim.x + threadIdx.x;
    if (i < XCNT) {
        float4 v = ((const float4*)x)[i];
        const int row = (i * 4) / D_DIM, d = (i * 4) % D_DIM;
        *(uint2*)(g_A + (size_t)row * K2 + d)          = split_hi(v);
        *(uint2*)(g_A + (size_t)row * K2 + D_DIM + d)  = split_lo(v);
    } else if (i < XCNT + WCNT) {
        const int j = i - XCNT;
        float4 v = ((const float4*)w1)[j];
        const int row = (j * 4) / D_DIM, d = (j * 4) % D_DIM;
        *(uint2*)(g_B + (size_t)row * K2 + d)          = split_hi(v);
        *(uint2*)(g_B + (size_t)row * K2 + D_DIM + d)  = split_lo(v);
    }
}

// ---------------------------------------------------------------------------
// Persistent HMMA GEMM (R8): 2 CTAs/SM, 2-stage cp.async
//   acc += A_hi·B_hi + A_lo·B_hi + A_hi·B_lo
// ---------------------------------------------------------------------------
#define SWZ(o) ((o) ^ (((o) >> 3) & 0x70))

__device__ __forceinline__ uint32_t s2u(const void* p) {
    uint32_t a;
    asm("{ .reg .u64 t; cvta.to.shared.u64 t, %1; cvt.u32.u64 %0, t; }"
        : "=r"(a) : "l"(p));
    return a;
}
__device__ __forceinline__ void cp16(uint32_t dst, const void* src) {
    asm volatile("cp.async.cg.shared.global [%0], [%1], 16;\n"
                 :: "r"(dst), "l"(src));
}
__device__ __forceinline__ void ldm4(uint32_t* r, uint32_t addr) {
    asm volatile("ldmatrix.sync.aligned.m8n8.x4.shared.b16 {%0,%1,%2,%3}, [%4];"
                 : "=r"(r[0]), "=r"(r[1]), "=r"(r[2]), "=r"(r[3]) : "r"(addr));
}
__device__ __forceinline__ void mma16816(float* c, const uint32_t* a, const uint32_t* b) {
    asm volatile("mma.sync.aligned.m16n8k16.row.col.f32.bf16.bf16.f32 "
                 "{%0,%1,%2,%3}, {%4,%5,%6,%7}, {%8,%9}, {%0,%1,%2,%3};"
                 : "+f"(c[0]), "+f"(c[1]), "+f"(c[2]), "+f"(c[3])
                 : "r"(a[0]), "r"(a[1]), "r"(a[2]), "r"(a[3]),
                   "r"(b[0]), "r"(b[1]));
}

static constexpr int A_T  = TM * 128;          // 16 KB
static constexpr int B_T  = TN * 128;          // 8 KB
static constexpr int STAGE_B = 2 * A_T + 2 * B_T;   // 48 KB
static constexpr int SMEM_BYTES = 2 * STAGE_B + 1024;

__global__ __launch_bounds__(256, 2)
void gemm_mma_kernel(const float* __restrict__ b1)
{
    extern __shared__ char smem[];
    const uint32_t sb = (s2u(smem) + 1023) & ~1023u;

    const int tid  = threadIdx.x;
    const int wid  = tid >> 5, lane = tid & 31;
    const int wm   = wid & 3;          // 4 warps in M
    const int wn   = wid >> 2;         // 2 warps in N

    const uint32_t STG[2] = { sb, sb + STAGE_B };

    uint32_t a_off[2], a_xr[2];
    #pragma unroll
    for (int i = 0; i < 2; i++) {
        int row = wm * 32 + i * 16 + (lane & 15);
        a_off[i] = row * 128;
        a_xr[i]  = (row & 7) << 4;
    }
    const uint32_t a_kh = (lane >> 4) * 16;

    uint32_t b_off[2], b_xr[2];
    #pragma unroll
    for (int j2 = 0; j2 < 2; j2++) {
        int row = wn * 32 + j2 * 16 + (lane & 7) + ((lane >> 4) & 1) * 8;
        b_off[j2] = row * 128;
        b_xr[j2]  = (row & 7) << 4;
    }
    const uint32_t b_kh = ((lane >> 3) & 1) * 16;

    const int l_r  = tid >> 3;      // 0..31
    const int l_c8 = tid & 7;

    for (int t = blockIdx.x; t < NTILES; t += gridDim.x) {
        const int bm = (t / (D_DIM / TN)) * TM;
        const int bn = (t % (D_DIM / TN)) * TN;

        auto load_stage = [&](int s, int k0) {
            const uint32_t st = STG[s];
            #pragma unroll
            for (int i = 0; i < 4; i++) {
                const int r = l_r + i * 32;
                uint32_t dsw = SWZ(r * 128 + l_c8 * 16);
                const __nv_bfloat16* arow = g_A + (size_t)(bm + r) * K2 + k0 + l_c8 * 8;
                cp16(st       + dsw, arow);
                cp16(st + A_T + dsw, arow + D_DIM);
            }
            #pragma unroll
            for (int i = 0; i < 2; i++) {
                const int r = l_r + i * 32;
                uint32_t dsw = SWZ(r * 128 + l_c8 * 16);
                const __nv_bfloat16* brow = g_B + (size_t)(bn + r) * K2 + k0 + l_c8 * 8;
                cp16(st + 2 * A_T       + dsw, brow);
                cp16(st + 2 * A_T + B_T + dsw, brow + D_DIM);
            }
        };

        float acc[2][4][4] = {};

        load_stage(0, 0);
        asm volatile("cp.async.commit_group;" ::: "memory");

        for (int ch = 0; ch < NCH; ch++) {
            const int cur = ch & 1, nxt = cur ^ 1;
            if (ch + 1 < NCH) {
                load_stage(nxt, (ch + 1) * 64);
                asm volatile("cp.async.commit_group;" ::: "memory");
                asm volatile("cp.async.wait_group 1;" ::: "memory");
            } else {
                asm volatile("cp.async.wait_group 0;" ::: "memory");
            }
            __syncthreads();

            const uint32_t AH = STG[cur];
            const uint32_t AL = AH + A_T;
            const uint32_t BH = AH + 2 * A_T;
            const uint32_t BL = BH + B_T;

            #pragma unroll
            for (int ks = 0; ks < 4; ks++) {
                const uint32_t kb = ks * 32;
                uint32_t ah[2][4], al[2][4], bh[2][4], bl[2][4];
                #pragma unroll
                for (int i = 0; i < 2; i++) {
                    uint32_t off = a_off[i] + ((kb + a_kh) ^ a_xr[i]);
                    ldm4(ah[i], AH + off);
                    ldm4(al[i], AL + off);
                }
                #pragma unroll
                for (int j2 = 0; j2 < 2; j2++) {
                    uint32_t off = b_off[j2] + ((kb + b_kh) ^ b_xr[j2]);
                    ldm4(bh[j2], BH + off);
                    ldm4(bl[j2], BL + off);
                }
                #pragma unroll
                for (int i = 0; i < 2; i++) {
                    #pragma unroll
                    for (int j = 0; j < 4; j++) {
                        const uint32_t* bhp = bh[j >> 1] + (j & 1) * 2;
                        const uint32_t* blp = bl[j >> 1] + (j & 1) * 2;
                        mma16816(acc[i][j], ah[i], bhp);
                        mma16816(acc[i][j], al[i], bhp);
                        mma16816(acc[i][j], ah[i], blp);
                    }
                }
            }
            __syncthreads();
        }

        // epilogue: bias + exact GELU
        const int r0 = lane >> 2;
        const int c0 = (lane & 3) * 2;
        #pragma unroll
        for (int i = 0; i < 2; i++) {
            const int m0 = bm + wm * 32 + i * 16 + r0;
            #pragma unroll
            for (int j = 0; j < 4; j++) {
                const int col = bn + wn * 32 + j * 8 + c0;
                const float bb0 = __ldg(&b1[col]);
                const float bb1 = __ldg(&b1[col + 1]);
                #pragma unroll
                for (int half = 0; half < 2; half++) {
                    const int m = m0 + half * 8;
                    float v0 = acc[i][j][half * 2 + 0] + bb0;
                    float v1 = acc[i][j][half * 2 + 1] + bb1;
                    float g0 = 0.5f * v0 * (1.0f + erff(v0 * 0.70710678118654752440f));
                    float g1 = 0.5f * v1 * (1.0f + erff(v1 * 0.70710678118654752440f));
                    *(float2*)(g_h + (size_t)m * D_DIM + col) = make_float2(g0, g1);
                }
            }
        }
        __syncthreads();
    }
}

// ---------------------------------------------------------------------------
// Kernel B: 8 rows/block, warp-per-row LN (no barriers in reductions),
// dot phase shares each w2 row across 8 resident rows.
// ---------------------------------------------------------------------------
__constant__ float c_bb[3][3] = {
    {-0.525f, 1.363f, 0.0f},
    { 0.0f,   0.0f,   0.0f},
    { 1.526f, 0.0f,   0.0f}
};

__global__ __launch_bounds__(256)
void ln_head_kernel(const float* __restrict__ ln_g,
                    const float* __restrict__ ln_b,
                    const float* __restrict__ w2,
                    const float* __restrict__ b2,
                    const float* __restrict__ affine,
                    const int*   __restrict__ mask,
                    float* __restrict__ out)
{
    const int tid  = threadIdx.x;
    const int wid  = tid >> 5, lane = tid & 31;
    const int row0 = blockIdx.x * 8;
    const int row  = row0 + wid;           // one warp per row

    __shared__ float sh[8][D_DIM];
    __shared__ float pbuf[8][12];

    // ---- LN: warp-local, 12 float4 (48 floats) per lane ----
    const float4* h4 = (const float4*)(g_h + (size_t)row * D_DIM);
    float4 l[12];
    float s = 0.0f;
    #pragma unroll
    for (int j = 0; j < 12; j++) {
        l[j] = h4[lane + j * 32];
        s += (l[j].x + l[j].y) + (l[j].z + l[j].w);
    }
    #pragma unroll
    for (int o = 16; o; o >>= 1) s += __shfl_xor_sync(0xFFFFFFFFu, s, o);
    const float mu = s * (1.0f / D_DIM);

    float s2 = 0.0f;
    #pragma unroll
    for (int j = 0; j < 12; j++) {
        float dx = l[j].x - mu, dy = l[j].y - mu, dz = l[j].z - mu, dw = l[j].w - mu;
        s2 += dx * dx + dy * dy + dz * dz + dw * dw;
    }
    #pragma unroll
    for (int o = 16; o; o >>= 1) s2 += __shfl_xor_sync(0xFFFFFFFFu, s2, o);
    const float inv = rsqrtf(s2 * (1.0f / D_DIM) + 1e-5f);

    const float4* g4 = (const float4*)ln_g;
    const float4* b4 = (const float4*)ln_b;
    #pragma unroll
    for (int j = 0; j < 12; j++) {
        const int idx = lane + j * 32;
        float4 g = g4[idx], b = b4[idx];
        float4 r;
        r.x = (l[j].x - mu) * inv * g.x + b.x;
        r.y = (l[j].y - mu) * inv * g.y + b.y;
        r.z = (l[j].z - mu) * inv * g.z + b.z;
        r.w = (l[j].w - mu) * inv * g.w + b.w;
        ((float4*)sh[wid])[idx] = r;
    }
    __syncthreads();

    // ---- dot: warp w does output o=w (and o=8 for w==0) against all 8 rows ----
    for (int o = wid; o < NGEO; o += 8) {
        const float4* w4 = (const float4*)(w2 + (size_t)o * D_DIM);
        float a[8] = {};
        #pragma unroll 4
        for (int d4 = lane; d4 < D_DIM / 4; d4 += 32) {
            float4 w = w4[d4];
            #pragma unroll
            for (int r = 0; r < 8; r++) {
                float4 h = ((const float4*)sh[r])[d4];
                a[r] = fmaf(w.x, h.x, fmaf(w.y, h.y, fmaf(w.z, h.z, fmaf(w.w, h.w, a[r]))));
            }
        }
        #pragma unroll
        for (int off = 16; off; off >>= 1) {
            #pragma unroll
            for (int r = 0; r < 8; r++)
                a[r] += __shfl_xor_sync(0xFFFFFFFFu, a[r], off);
        }
        if (lane == 0) {
            const float bb = b2[o];
            #pragma unroll
            for (int r = 0; r < 8; r++) pbuf[r][o] = a[r] + bb;
        }
    }
    __syncthreads();

    // ---- geometry: threads 0..7, one row each ----
    if (tid < 8) {
        const int r = row0 + tid;
        const float* p = pbuf[tid];
        float trans[3], xv[3], yv[3];
        #pragma unroll
        for (int i = 0; i < 3; i++) {
            trans[i] = p[i] * 10.0f;
            xv[i]    = p[3 + i];
            yv[i]    = p[6 + i];
        }
        float xn = sqrtf(xv[0]*xv[0] + xv[1]*xv[1] + xv[2]*xv[2]) + 1e-5f;
        float yn = sqrtf(yv[0]*yv[0] + yv[1]*yv[1] + yv[2]*yv[2]) + 1e-5f;
        #pragma unroll
        for (int i = 0; i < 3; i++) { xv[i] /= xn; yv[i] /= yn; }

        float ax[3] = { -xv[0], -xv[1], -xv[2] };
        float n0 = rsqrtf(ax[0]*ax[0] + ax[1]*ax[1] + ax[2]*ax[2] + 1e-12f);
        float e0[3] = { ax[0]*n0, ax[1]*n0, ax[2]*n0 };
        float c = e0[0]*yv[0] + e0[1]*yv[1] + e0[2]*yv[2];
        float e1[3] = { yv[0] - e0[0]*c, yv[1] - e0[1]*c, yv[2] - e0[2]*c };
        float n1 = rsqrtf(e1[0]*e1[0] + e1[1]*e1[1] + e1[2]*e1[2] + 1e-12f);
        e1[0] *= n1; e1[1] *= n1; e1[2] *= n1;
        float e2[3] = { e0[1]*e1[2] - e0[2]*e1[1],
                        e0[2]*e1[0] - e0[0]*e1[2],
                        e0[0]*e1[1] - e0[1]*e1[0] };

        float Ru[3][3] = {
            { e0[0], e1[0], e2[0] },
            { e0[1], e1[1], e2[1] },
            { e0[2], e1[2], e2[2] }
        };
        float tu[3] = { trans[0], trans[1], trans[2] };

        if (mask[r] == 0) {
            #pragma unroll
            for (int i = 0; i < 3; i++) {
                #pragma unroll
                for (int j = 0; j < 3; j++) Ru[i][j] = (i == j) ? 1.0f : 0.0f;
                tu[i] = 0.0f;
            }
        }

        const float* af = affine + (size_t)r * 12;
        float R0[3][3], t0[3];
        #pragma unroll
        for (int i = 0; i < 3; i++) {
            #pragma unroll
            for (int j = 0; j < 3; j++) R0[i][j] = af[i * 3 + j];
            t0[i] = af[9 + i];
        }

        float R[3][3], tt[3];
        #pragma unroll
        for (int i = 0; i < 3; i++) {
            #pragma unroll
            for (int j = 0; j < 3; j++) {
                float a = 0.0f;
                #pragma unroll
                for (int k = 0; k < 3; k++) a = fmaf(R0[i][k], Ru[k][j], a);
                R[i][j] = a;
            }
            float ta = t0[i];
            #pragma unroll
            for (int j = 0; j < 3; j++) ta = fmaf(R0[i][j], tu[j], ta);
            tt[i] = ta;
        }

        float* ao = out + (size_t)r * 12;
        #pragma unroll
        for (int i = 0; i < 3; i++)
            #pragma unroll
            for (int j = 0; j < 3; j++) ao[i * 3 + j] = R[i][j];
        #pragma unroll
        for (int i = 0; i < 3; i++) ao[9 + i] = tt[i];

        float* po = out + (size_t)M_TOT * 12 + (size_t)r * 9;
        #pragma unroll
        for (int a = 0; a < 3; a++) {
            #pragma unroll
            for (int i = 0; i < 3; i++) {
                float v = tt[i];
                #pragma unroll
                for (int j = 0; j < 3; j++) v = fmaf(R[i][j], c_bb[a][j], v);
                po[a * 3 + i] = v;
            }
        }
    }
}

// ---------------------------------------------------------------------------
extern "C" void kernel_launch(void* const* d_in, const int* in_sizes, int n_in,
                              void* d_out, int out_size)
{
    const float* x      = (const float*)d_in[0];
    const float* affine = (const float*)d_in[1];
    const int*   amask  = (const int*)  d_in[2];
    const float* w1     = (const float*)d_in[3];
    const float* b1     = (const float*)d_in[4];
    const float* ln_g   = (const float*)d_in[5];
    const float* ln_b   = (const float*)d_in[6];
    const float* w2     = (const float*)d_in[7];
    const float* b2     = (const float*)d_in[8];
    float* out = (float*)d_out;

    cudaFuncSetAttribute(gemm_mma_kernel,
                         cudaFuncAttributeMaxDynamicSharedMemorySize, SMEM_BYTES);

    int sms = 148;
    cudaDeviceGetAttribute(&sms, cudaDevAttrMultiProcessorCount, 0);

    conv_all_kernel<<<(XCNT + WCNT + 255) / 256, 256>>>(x, w1);

    gemm_mma_kernel<<<sms * 2, 256, SMEM_BYTES>>>(b1);

    ln_head_kernel<<<M_TOT / 8, 256>>>(ln_g, ln_b, w2, b2, affine, amask, out);
}